// round 5
// baseline (speedup 1.0000x reference)
#include <cuda_runtime.h>
#include <cstdint>

// Problem constants
#define N_PIX 4194304      // 4*4*512*512
#define NQ    1048576      // N_PIX / 4  (float4 groups)
#define NB    101          // bins / categories
#define RSTR  104          // padded row stride (floats): 16B-aligned rows
#define NBK   64           // u-quantile buckets per row

// ---------------------------------------------------------------------------
// JAX *partitionable* threefry bits for 32-bit draws, key = jax.random.key(1):
//   (k1,k2) = (0,1);  ks0=0, ks1=1, ks2 = 0^1^0x1BD11BDA = 0x1BD11BDB
//   per element i (size < 2^32): counts_hi = 0, counts_lo = i
//   (y0,y1) = threefry2x32((0,1), (0,i));  bits = y0 ^ y1
// ---------------------------------------------------------------------------
__device__ __forceinline__ uint32_t threefry_bits(uint32_t i) {
    const uint32_t ks0 = 0u;
    const uint32_t ks1 = 1u;
    const uint32_t ks2 = 0x1BD11BDBu;

    uint32_t x0 = 0u + ks0;
    uint32_t x1 = i  + ks1;

#define TF_ROUND(r) do { x0 += x1; x1 = __funnelshift_l(x1, x1, (r)); x1 ^= x0; } while (0)

    TF_ROUND(13); TF_ROUND(15); TF_ROUND(26); TF_ROUND(6);
    x0 += ks1; x1 += ks2 + 1u;
    TF_ROUND(17); TF_ROUND(29); TF_ROUND(16); TF_ROUND(24);
    x0 += ks2; x1 += ks0 + 2u;
    TF_ROUND(13); TF_ROUND(15); TF_ROUND(26); TF_ROUND(6);
    x0 += ks0; x1 += ks1 + 3u;
    TF_ROUND(17); TF_ROUND(29); TF_ROUND(16); TF_ROUND(24);
    x0 += ks1; x1 += ks2 + 4u;
    TF_ROUND(13); TF_ROUND(15); TF_ROUND(26); TF_ROUND(6);
    x0 += ks2; x1 += ks0 + 5u;

#undef TF_ROUND
    return x0 ^ x1;           // partitionable 32-bit combine
}

// digitize(x, arange(0,0.5,0.005)) = # of float32 edges e(j)=j*0.005f with e<=x
__device__ __forceinline__ int refl_bin(float xv) {
    int r = (int)(xv * 200.0f) + 1;
    r = min(r, 100);
    if (r < 100 && (float)r * 0.005f <= xv) ++r;
    if ((float)(r - 1) * 0.005f > xv) --r;
    return r;   // in [0, 100]
}

// Shared state (static; 42,016 + 6,464 = 48,480 B < 48 KB)
// cdf: padded rows, pad values = 2.0f (never < u since u < 1)
// tbl[r][k] = first j with cdf[r][j] >= k/64  (exact fp32 thresholds)
struct SmemState {
    float   cdf[NB * RSTR];
    uint8_t tbl[NB * NBK];
};

// searchsorted(cdf_row, u, 'left') via bucket table + aligned 8-float window.
__device__ __forceinline__ int sample_idx(const float* __restrict__ cdf,
                                          const uint8_t* __restrict__ tbl,
                                          int r, float u) {
    int k = (int)(u * 64.0f);
    k = min(k, NBK - 1);
    // exact-rounding fixup: thresholds k/64 are exact floats
    if ((float)k * 0.015625f > u) --k;   // k >= 0 since u >= 0

    int s  = tbl[r * NBK + k];
    int s4 = min(s & ~3, 96);            // window always inside padded row

    const float4* rowq = (const float4*)(cdf + r * RSTR);  // 16B-aligned
    float4 w0 = rowq[(s4 >> 2)];
    float4 w1 = rowq[(s4 >> 2) + 1];

    int c = (w0.x < u) + (w0.y < u) + (w0.z < u) + (w0.w < u)
          + (w1.x < u) + (w1.y < u) + (w1.z < u) + (w1.w < u);
    int j = s4 + c;

    if (c == 8) {                        // rare overflow: linear scan
        const float* row = cdf + r * RSTR;
        j = s4 + 8;
        while (j < NB && row[j] < u) ++j;
    }
    return min(j, NB - 1);
}

__global__ __launch_bounds__(1024, 2)
void noise_model_kernel(const float4* __restrict__ x4,
                        const float*  __restrict__ nm,
                        float4* __restrict__ out4) {
    __shared__ __align__(16) SmemState sm;

    const int tid = threadIdx.x;

    // Per-block build: thread t handles row t (cumsum + bucket table).
    if (tid < NB) {
        const float* rowp = nm + tid * NB;
        float*       crow = sm.cdf + tid * RSTR;
        float s = 0.0f;
#pragma unroll 4
        for (int j = 0; j < NB; ++j) {
            s += rowp[j];
            crow[j] = s;
        }
        crow[101] = 2.0f; crow[102] = 2.0f; crow[103] = 2.0f;  // pads

        // two-pointer bucket table: tbl[k] = first j with crow[j] >= k/64
        uint8_t* trow = sm.tbl + tid * NBK;
        int j = 0;
#pragma unroll 1
        for (int k = 0; k < NBK; ++k) {
            float t = (float)k * 0.015625f;   // exact
            while (j < NB && crow[j] < t) ++j;
            trow[k] = (uint8_t)j;
        }
    }
    __syncthreads();

    const int stride = blockDim.x * gridDim.x;
    for (int g = blockIdx.x * blockDim.x + tid; g < NQ; g += stride) {
        const uint32_t base = (uint32_t)g * 4u;

        // 4 independent threefry evaluations (ILP)
        uint32_t b0 = threefry_bits(base + 0u);
        uint32_t b1 = threefry_bits(base + 1u);
        uint32_t b2 = threefry_bits(base + 2u);
        uint32_t b3 = threefry_bits(base + 3u);

        float u0 = __uint_as_float((b0 >> 9) | 0x3f800000u) - 1.0f;
        float u1 = __uint_as_float((b1 >> 9) | 0x3f800000u) - 1.0f;
        float u2 = __uint_as_float((b2 >> 9) | 0x3f800000u) - 1.0f;
        float u3 = __uint_as_float((b3 >> 9) | 0x3f800000u) - 1.0f;

        float4 xv = x4[g];

        int i0 = sample_idx(sm.cdf, sm.tbl, refl_bin(xv.x), u0);
        int i1 = sample_idx(sm.cdf, sm.tbl, refl_bin(xv.y), u1);
        int i2 = sample_idx(sm.cdf, sm.tbl, refl_bin(xv.z), u2);
        int i3 = sample_idx(sm.cdf, sm.tbl, refl_bin(xv.w), u3);

        float4 o;
        o.x = -0.0101f + 0.0002f * (float)i0;
        o.y = -0.0101f + 0.0002f * (float)i1;
        o.z = -0.0101f + 0.0002f * (float)i2;
        o.w = -0.0101f + 0.0002f * (float)i3;
        out4[g] = o;
    }
}

extern "C" void kernel_launch(void* const* d_in, const int* in_sizes, int n_in,
                              void* d_out, int out_size) {
    // Disambiguate inputs by size: x has 4194304 elems, noise_matrix has 10201.
    const float* a = (const float*)d_in[0];
    const float* b = (const float*)d_in[1];
    const float* x  = a;
    const float* nm = b;
    if (n_in >= 2 && in_sizes[0] < in_sizes[1]) { x = b; nm = a; }
    float* out = (float*)d_out;
    (void)out_size;

    noise_model_kernel<<<296, 1024>>>((const float4*)x, nm, (float4*)out);
}